// round 7
// baseline (speedup 1.0000x reference)
#include <cuda_runtime.h>
#include <cuda_bf16.h>
#include <math.h>

// Problem dims
#define BB   16
#define KC   64
#define WW   2048
#define LL   2112      // KC + WW
#define DD   512
#define DHH  256
#define DFFF 2048
#define NLL  4
#define LN_EPS 1e-5f

// ---------------------------------------------------------------------------
// Device scratch
// ---------------------------------------------------------------------------
__device__ float g_h  [BB * LL * DD];
__device__ float g_hn [BB * LL * DD];
__device__ float g_q  [BB * LL * DHH];
__device__ float g_k  [BB * WW * DHH];
__device__ float g_v  [BB * WW * DHH];
__device__ float g_s  [BB * LL * WW];     // scores / FFN mid
__device__ float g_cat[BB * LL * DD];

// ---------------------------------------------------------------------------
// Embedding
// ---------------------------------------------------------------------------
__global__ void embed_kernel(const int* __restrict__ cache, const int* __restrict__ seq,
                             const float* __restrict__ item, const float* __restrict__ cpos,
                             const float* __restrict__ spos, const float* __restrict__ seg,
                             float* __restrict__ h) {
    int r = blockIdx.x;
    int b = r / LL, l = r % LL;
    int idx; const float* pos; const float* sg;
    if (l < KC) { idx = cache[b * KC + l]; pos = cpos + (long)l * DD; sg = seg; }
    else        { int i = l - KC; idx = seq[b * WW + i]; pos = spos + (long)i * DD; sg = seg + DD; }
    const float* it = item + (long)idx * DD;
    float* hr = h + (long)r * DD;
    for (int d = threadIdx.x; d < DD; d += blockDim.x)
        hr[d] = it[d] + pos[d] + sg[d];
}

// ---------------------------------------------------------------------------
// LayerNorm: grid (rows, BB)
// ---------------------------------------------------------------------------
__global__ void ln_kernel(const float* __restrict__ x, float* __restrict__ y,
                          const float* __restrict__ g, const float* __restrict__ bia) {
    __shared__ float rs[256], rq[256];
    long row = (long)blockIdx.y * LL + blockIdx.x;
    const float* xr = x + row * DD;
    float* yr = y + row * DD;
    int t = threadIdx.x;
    float v0 = xr[t], v1 = xr[t + 256];
    rs[t] = v0 + v1; rq[t] = v0 * v0 + v1 * v1; __syncthreads();
    for (int o = 128; o > 0; o >>= 1) {
        if (t < o) { rs[t] += rs[t + o]; rq[t] += rq[t + o]; }
        __syncthreads();
    }
    float mean = rs[0] * (1.0f / DD);
    float var  = rq[0] * (1.0f / DD) - mean * mean;
    float inv  = rsqrtf(var + LN_EPS);
    yr[t]       = (v0 - mean) * inv * g[t]       + bia[t];
    yr[t + 256] = (v1 - mean) * inv * g[t + 256] + bia[t + 256];
}

// ---------------------------------------------------------------------------
// bf16x3 split tensor-core batched GEMM, register-prefetch pipelined,
// packed-quad smem for LDS.128/LDS.64 fragment loads.
// C = alpha*A@B (+bias) (+relu) (+C residual)
// A (M,Kd) row-major; B (Kd,N) row-major, or (N,Kd) when TRANSB.
// Block tile 128x128x32, 8 warps (2x4), warp tile 64x32, mma m16n8k16 bf16.
// Kd multiple of 32; M,N arbitrary (clamped loads, predicated stores, N even).
//
// smem layouts (j = k-pair index 0..15; row = (j&3) + (j>>3)*4; khalf=(j>>2)&1):
//   A planes: word = q*4 + khalf*2 + mb, q = (m&7) + (m>>4)*8, mb = (m>>3)&1
//             -> one mma A-fragment (4 regs) = one aligned LDS.128
//   B planes: word = n*2 + khalf
//             -> one mma B-fragment (2 regs) = one aligned LDS.64
// Row stride 264 words (mod 32 = 8) => conflict-free fragment loads.
// ---------------------------------------------------------------------------
#define FLAG_RES  1
#define FLAG_RELU 2

__device__ __forceinline__ void split2(float x, float y, unsigned& hi, unsigned& lo) {
    __nv_bfloat16 hx = __float2bfloat16_rn(x);
    __nv_bfloat16 hy = __float2bfloat16_rn(y);
    float rx = x - __bfloat162float(hx);
    float ry = y - __bfloat162float(hy);
    __nv_bfloat16 lx = __float2bfloat16_rn(rx);
    __nv_bfloat16 ly = __float2bfloat16_rn(ry);
    hi = ((unsigned)__bfloat16_as_ushort(hy) << 16) | (unsigned)__bfloat16_as_ushort(hx);
    lo = ((unsigned)__bfloat16_as_ushort(ly) << 16) | (unsigned)__bfloat16_as_ushort(lx);
}

__device__ __forceinline__ void mma_bf16(float* c, const unsigned* a, const unsigned* b) {
    asm volatile(
        "mma.sync.aligned.m16n8k16.row.col.f32.bf16.bf16.f32 "
        "{%0,%1,%2,%3}, {%4,%5,%6,%7}, {%8,%9}, {%0,%1,%2,%3};"
        : "+f"(c[0]), "+f"(c[1]), "+f"(c[2]), "+f"(c[3])
        : "r"(a[0]), "r"(a[1]), "r"(a[2]), "r"(a[3]), "r"(b[0]), "r"(b[1]));
}

template <bool TRANSB>
__global__ __launch_bounds__(256)
void gemm_tc(const float* __restrict__ A, int lda, long sA,
             const float* __restrict__ Bm, int ldb, long sB,
             float* __restrict__ C, int ldc, long sC,
             int M, int N, int Kd, float alpha,
             const float* __restrict__ bias, int flags) {
    __shared__ unsigned Ah[8][264], Al[8][264];
    __shared__ unsigned Bh[8][264], Bl[8][264];

    A  += (long)blockIdx.z * sA;
    Bm += (long)blockIdx.z * sB;
    C  += (long)blockIdx.z * sC;
    const int m0 = blockIdx.y * 128, n0 = blockIdx.x * 128;

    const int tid  = threadIdx.x;
    const int lane = tid & 31;
    const int warp = tid >> 5;
    const int wm = (warp >> 2) * 64;
    const int wn = (warp & 3) * 32;
    const int r = lane >> 2, c = lane & 3;

    float acc[4][4][4] = {{{0.f}}};

    // ---- A global-load mapping: thread covers 16 consecutive k of one row ----
    const int am    = tid & 127;
    const int akq   = (tid >> 7) * 16;       // 0 or 16
    const int jbase = akq >> 1;              // 0 or 8
    const int aq4   = ((am & 7) + ((am >> 4) & 7) * 8) * 4 + ((am >> 3) & 1);
    const float* Aptr = A + (long)min(m0 + am, M - 1) * lda + akq;

    // ---- B global-load mapping ----
    const float* Bptr;
    int n2 = 0, bkrow = 0;
    if (TRANSB) {
        Bptr = Bm + (long)min(n0 + am, N - 1) * ldb + akq;
    } else {
        n2    = (tid & 63) * 2;
        bkrow = tid >> 6;                    // 0..3
        Bptr  = Bm + min(n0 + n2, N - 2);
    }

    // ---- prefetch registers ----
    float4 apf[4];
    float4 bpf[4];     // TRANSB
    float2 vpf[8];     // !TRANSB: pairs (row 2j, row 2j+1)

#pragma unroll
    for (int i = 0; i < 4; i++) apf[i] = *(const float4*)(Aptr + i * 4);
    if (TRANSB) {
#pragma unroll
        for (int i = 0; i < 4; i++) bpf[i] = *(const float4*)(Bptr + i * 4);
    } else {
#pragma unroll
        for (int i = 0; i < 4; i++) {
            int j = bkrow + i * 4;
            vpf[2 * i]     = *(const float2*)(Bptr + (long)(2 * j) * ldb);
            vpf[2 * i + 1] = *(const float2*)(Bptr + (long)(2 * j + 1) * ldb);
        }
    }

    for (int k0 = 0; k0 < Kd; k0 += 32) {
        // ---- stage current tile (split fp32 -> bf16 hi/lo, packed layout) ----
#pragma unroll
        for (int i = 0; i < 4; i++) {
            int j0 = jbase + 2 * i;
            {
                int row = (j0 & 3) + (j0 >> 3) * 4;
                int w = aq4 + ((j0 >> 2) & 1) * 2;
                split2(apf[i].x, apf[i].y, Ah[row][w], Al[row][w]);
            }
            {
                int j1 = j0 + 1;
                int row = (j1 & 3) + (j1 >> 3) * 4;
                int w = aq4 + ((j1 >> 2) & 1) * 2;
                split2(apf[i].z, apf[i].w, Ah[row][w], Al[row][w]);
            }
        }
        if (TRANSB) {
            const int bw = am * 2;
#pragma unroll
            for (int i = 0; i < 4; i++) {
                int j0 = jbase + 2 * i;
                {
                    int row = (j0 & 3) + (j0 >> 3) * 4;
                    int w = bw + ((j0 >> 2) & 1);
                    split2(bpf[i].x, bpf[i].y, Bh[row][w], Bl[row][w]);
                }
                {
                    int j1 = j0 + 1;
                    int row = (j1 & 3) + (j1 >> 3) * 4;
                    int w = bw + ((j1 >> 2) & 1);
                    split2(bpf[i].z, bpf[i].w, Bh[row][w], Bl[row][w]);
                }
            }
        } else {
#pragma unroll
            for (int i = 0; i < 4; i++) {
                int j = bkrow + i * 4;
                int row = (j & 3) + (j >> 3) * 4;
                int kh = (j >> 2) & 1;
                split2(vpf[2 * i].x, vpf[2 * i + 1].x, Bh[row][n2 * 2 + kh],       Bl[row][n2 * 2 + kh]);
                split2(vpf[2 * i].y, vpf[2 * i + 1].y, Bh[row][(n2 + 1) * 2 + kh], Bl[row][(n2 + 1) * 2 + kh]);
            }
        }
        __syncthreads();

        // ---- prefetch next tile while computing this one ----
        if (k0 + 32 < Kd) {
#pragma unroll
            for (int i = 0; i < 4; i++) apf[i] = *(const float4*)(Aptr + k0 + 32 + i * 4);
            if (TRANSB) {
#pragma unroll
                for (int i = 0; i < 4; i++) bpf[i] = *(const float4*)(Bptr + k0 + 32 + i * 4);
            } else {
#pragma unroll
                for (int i = 0; i < 4; i++) {
                    int j = bkrow + i * 4;
                    vpf[2 * i]     = *(const float2*)(Bptr + (long)(k0 + 32 + 2 * j) * ldb);
                    vpf[2 * i + 1] = *(const float2*)(Bptr + (long)(k0 + 32 + 2 * j + 1) * ldb);
                }
            }
        }

        // ---- compute: 2 mma k-steps of 16 ----
#pragma unroll
        for (int kh = 0; kh < 2; kh++) {
            const int rowb = kh * 4 + c;
            uint4 ah[4], al[4];
            uint2 bh[4], bl[4];
#pragma unroll
            for (int mf = 0; mf < 4; mf++) {
                int off = (r + ((wm >> 4) + mf) * 8) * 4;
                ah[mf] = *(const uint4*)&Ah[rowb][off];
                al[mf] = *(const uint4*)&Al[rowb][off];
            }
#pragma unroll
            for (int nf = 0; nf < 4; nf++) {
                int off = (wn + nf * 8 + r) * 2;
                bh[nf] = *(const uint2*)&Bh[rowb][off];
                bl[nf] = *(const uint2*)&Bl[rowb][off];
            }
#pragma unroll
            for (int mf = 0; mf < 4; mf++)
#pragma unroll
                for (int nf = 0; nf < 4; nf++) {
                    mma_bf16(acc[mf][nf], (const unsigned*)&ah[mf], (const unsigned*)&bh[nf]);
                    mma_bf16(acc[mf][nf], (const unsigned*)&ah[mf], (const unsigned*)&bl[nf]);
                    mma_bf16(acc[mf][nf], (const unsigned*)&al[mf], (const unsigned*)&bh[nf]);
                }
        }
        __syncthreads();
    }

    // ---- epilogue ----
#pragma unroll
    for (int mf = 0; mf < 4; mf++) {
        int r0 = m0 + wm + mf * 16 + r;
#pragma unroll
        for (int nf = 0; nf < 4; nf++) {
            int cc = n0 + wn + nf * 8 + c * 2;
            if (cc < N) {
#pragma unroll
                for (int half = 0; half < 2; half++) {
                    int rr = r0 + half * 8;
                    if (rr < M) {
                        float v0 = alpha * acc[mf][nf][half * 2 + 0];
                        float v1 = alpha * acc[mf][nf][half * 2 + 1];
                        if (bias) { v0 += bias[cc]; v1 += bias[cc + 1]; }
                        if (flags & FLAG_RELU) { v0 = fmaxf(v0, 0.f); v1 = fmaxf(v1, 0.f); }
                        long base = (long)rr * ldc + cc;
                        if (flags & FLAG_RES) { v0 += C[base]; v1 += C[base + 1]; }
                        C[base] = v0; C[base + 1] = v1;
                    }
                }
            }
        }
    }
}

// ---------------------------------------------------------------------------
// Softmax; grid (rows, BB); masked tail zeroed -> dense PV GEMM
// ---------------------------------------------------------------------------
__global__ void softmax_kernel(float* __restrict__ S, int ncols, int rows, int causal) {
    __shared__ float red[256];
    int l = blockIdx.x, b = blockIdx.y;
    float* p = S + ((long)b * rows + l) * ncols;
    int valid = causal ? (l < KC ? ncols : (l - KC + 1)) : ncols;
    int t = threadIdx.x;

    float m = -1e30f;
    for (int i = t; i < valid; i += blockDim.x) m = fmaxf(m, p[i]);
    red[t] = m; __syncthreads();
    for (int o = 128; o > 0; o >>= 1) { if (t < o) red[t] = fmaxf(red[t], red[t + o]); __syncthreads(); }
    m = red[0]; __syncthreads();

    float s = 0.f;
    for (int i = t; i < valid; i += blockDim.x) { float e = expf(p[i] - m); p[i] = e; s += e; }
    red[t] = s; __syncthreads();
    for (int o = 128; o > 0; o >>= 1) { if (t < o) red[t] += red[t + o]; __syncthreads(); }
    float inv = 1.0f / red[0];

    for (int i = t; i < ncols; i += blockDim.x)
        p[i] = (i < valid) ? p[i] * inv : 0.f;
}

// ---------------------------------------------------------------------------
// Final LN over the K cache rows + dot with w_ev -> logits
// ---------------------------------------------------------------------------
__global__ void final_kernel(const float* __restrict__ h, const float* __restrict__ fg,
                             const float* __restrict__ fb, const float* __restrict__ wev,
                             const float* __restrict__ bev, float* __restrict__ out) {
    __shared__ float rs[256], rq[256];
    int l = blockIdx.x, b = blockIdx.y;
    const float* xr = h + ((long)b * LL + l) * DD;
    int t = threadIdx.x;
    float v0 = xr[t], v1 = xr[t + 256];
    rs[t] = v0 + v1; rq[t] = v0 * v0 + v1 * v1; __syncthreads();
    for (int o = 128; o > 0; o >>= 1) {
        if (t < o) { rs[t] += rs[t + o]; rq[t] += rq[t + o]; }
        __syncthreads();
    }
    float mean = rs[0] * (1.0f / DD);
    float inv  = rsqrtf(rq[0] * (1.0f / DD) - mean * mean + LN_EPS);
    __syncthreads();
    float d0 = ((v0 - mean) * inv * fg[t]       + fb[t])       * wev[t];
    float d1 = ((v1 - mean) * inv * fg[t + 256] + fb[t + 256]) * wev[t + 256];
    rs[t] = d0 + d1; __syncthreads();
    for (int o = 128; o > 0; o >>= 1) { if (t < o) rs[t] += rs[t + o]; __syncthreads(); }
    if (t == 0) out[b * KC + l] = rs[0] + bev[0];
}

// ---------------------------------------------------------------------------
// Host launcher
// ---------------------------------------------------------------------------
static void gemm(bool transb, const float* A, int lda, long sA,
                 const float* Bm, int ldb, long sB,
                 float* C, int ldc, long sC,
                 int M, int N, int Kd, float alpha,
                 const float* bias, int flags) {
    dim3 grid((N + 127) / 128, (M + 127) / 128, BB);
    if (transb)
        gemm_tc<true><<<grid, 256>>>(A, lda, sA, Bm, ldb, sB, C, ldc, sC, M, N, Kd, alpha, bias, flags);
    else
        gemm_tc<false><<<grid, 256>>>(A, lda, sA, Bm, ldb, sB, C, ldc, sC, M, N, Kd, alpha, bias, flags);
}

extern "C" void kernel_launch(void* const* d_in, const int* in_sizes, int n_in,
                              void* d_out, int out_size) {
    const int*   cache = (const int*)d_in[0];
    const int*   seq   = (const int*)d_in[1];
    const float* item  = (const float*)d_in[2];
    const float* cpos  = (const float*)d_in[3];
    const float* spos  = (const float*)d_in[4];
    const float* seg   = (const float*)d_in[5];
    const float* wq_s  = (const float*)d_in[6];
    const float* wk_s  = (const float*)d_in[7];
    const float* wv_s  = (const float*)d_in[8];
    const float* wq_c  = (const float*)d_in[9];
    const float* wk_c  = (const float*)d_in[10];
    const float* wv_c  = (const float*)d_in[11];
    const float* w_out = (const float*)d_in[12];
    const float* b_out = (const float*)d_in[13];
    const float* ln1g  = (const float*)d_in[14];
    const float* ln1b  = (const float*)d_in[15];
    const float* ln2g  = (const float*)d_in[16];
    const float* ln2b  = (const float*)d_in[17];
    const float* wff1  = (const float*)d_in[18];
    const float* bff1  = (const float*)d_in[19];
    const float* wff2  = (const float*)d_in[20];
    const float* bff2  = (const float*)d_in[21];
    const float* fing  = (const float*)d_in[22];
    const float* finb  = (const float*)d_in[23];
    const float* wev   = (const float*)d_in[24];
    const float* bev   = (const float*)d_in[25];
    float* out = (float*)d_out;

    float *h, *hn, *q, *k, *v, *s, *cat;
    cudaGetSymbolAddress((void**)&h,   g_h);
    cudaGetSymbolAddress((void**)&hn,  g_hn);
    cudaGetSymbolAddress((void**)&q,   g_q);
    cudaGetSymbolAddress((void**)&k,   g_k);
    cudaGetSymbolAddress((void**)&v,   g_v);
    cudaGetSymbolAddress((void**)&s,   g_s);
    cudaGetSymbolAddress((void**)&cat, g_cat);

    const float scale = 0.0625f;   // 1/sqrt(256)
    const long  sHL  = (long)LL * DD;

    embed_kernel<<<BB * LL, 256>>>(cache, seq, item, cpos, spos, seg, h);

    for (int l = 0; l < NLL; l++) {
        const float* Wq_s = wq_s + (long)l * DD * DHH;
        const float* Wk_s = wk_s + (long)l * DD * DHH;
        const float* Wv_s = wv_s + (long)l * DD * DHH;
        const float* Wq_c = wq_c + (long)l * DD * DHH;
        const float* Wk_c = wk_c + (long)l * DD * DHH;
        const float* Wv_c = wv_c + (long)l * DD * DHH;
        const float* Wo   = w_out + (long)l * DD * DD;
        const float* Bo   = b_out + (long)l * DD;
        const float* W1   = wff1 + (long)l * DD * DFFF;
        const float* B1   = bff1 + (long)l * DFFF;
        const float* W2   = wff2 + (long)l * DFFF * DD;
        const float* B2   = bff2 + (long)l * DD;

        // Last layer: only the K=64 cache rows feed the output head.
        const int Mq = (l == NLL - 1) ? KC : LL;
        const long sQ = (long)Mq * DHH;

        // ---- LN1 (full: K/V need every row) ----
        ln_kernel<<<dim3(LL, BB), 256>>>(h, hn, ln1g + l * DD, ln1b + l * DD);

        // ---- Attention A (seq keys, causal) ----
        gemm(false, hn, DD, sHL, Wq_s, DHH, 0, q, DHH, sQ, Mq, DHH, DD, 1.f, nullptr, 0);
        gemm(false, hn + (long)KC * DD, DD, sHL, Wk_s, DHH, 0, k, DHH, (long)WW * DHH, WW, DHH, DD, 1.f, nullptr, 0);
        gemm(false, hn + (long)KC * DD, DD, sHL, Wv_s, DHH, 0, v, DHH, (long)WW * DHH, WW, DHH, DD, 1.f, nullptr, 0);
        gemm(true, q, DHH, sQ, k, DHH, (long)WW * DHH, s, WW, (long)Mq * WW, Mq, WW, DHH, scale, nullptr, 0);
        softmax_kernel<<<dim3(Mq, BB), 256>>>(s, WW, Mq, 1);
        gemm(false, s, WW, (long)Mq * WW, v, DHH, (long)WW * DHH, cat, DD, sHL, Mq, DHH, WW, 1.f, nullptr, 0);

        // ---- Attention B (cache keys, no mask) ----
        gemm(false, hn, DD, sHL, Wq_c, DHH, 0, q, DHH, sQ, Mq, DHH, DD, 1.f, nullptr, 0);
        gemm(false, hn, DD, sHL, Wk_c, DHH, 0, k, DHH, (long)KC * DHH, KC, DHH, DD, 1.f, nullptr, 0);
        gemm(false, hn, DD, sHL, Wv_c, DHH, 0, v, DHH, (long)KC * DHH, KC, DHH, DD, 1.f, nullptr, 0);
        gemm(true, q, DHH, sQ, k, DHH, (long)KC * DHH, s, KC, (long)Mq * KC, Mq, KC, DHH, scale, nullptr, 0);
        softmax_kernel<<<dim3(Mq, BB), 256>>>(s, KC, Mq, 0);
        gemm(false, s, KC, (long)Mq * KC, v, DHH, (long)KC * DHH, cat + DHH, DD, sHL, Mq, DHH, KC, 1.f, nullptr, 0);

        // ---- Output projection + residual ----
        gemm(false, cat, DD, sHL, Wo, DD, 0, h, DD, sHL, Mq, DD, DD, 1.f, Bo, FLAG_RES);

        // ---- FFN ----
        ln_kernel<<<dim3(Mq, BB), 256>>>(h, hn, ln2g + l * DD, ln2b + l * DD);
        gemm(false, hn, DD, sHL, W1, DFFF, 0, s, DFFF, (long)Mq * DFFF, Mq, DFFF, DD, 1.f, B1, FLAG_RELU);
        gemm(false, s, DFFF, (long)Mq * DFFF, W2, DD, 0, h, DD, sHL, Mq, DD, DFFF, 1.f, B2, FLAG_RES);
    }

    final_kernel<<<dim3(KC, BB), 256>>>(h, fing, finb, wev, bev, out);
}

// round 9
// speedup vs baseline: 1.2151x; 1.2151x over previous
#include <cuda_runtime.h>
#include <cuda_bf16.h>
#include <math.h>

#define BB   16
#define KC   64
#define WW   2048
#define LL   2112
#define DD   512
#define DHH  256
#define DFFF 2048
#define NLL  4
#define LN_EPS 1e-5f

typedef __nv_bfloat16 bf16;

// ---------------------------------------------------------------------------
// Device scratch (statics; no allocations allowed)
// ---------------------------------------------------------------------------
__device__ float g_h [(long)BB*LL*DD];          // residual (fp32)
__device__ float g_s [(long)BB*LL*WW];          // scores fp32
__device__ bf16 g_hn2 [(long)BB*LL*2*DD];       // LN out   [hi|lo]
__device__ bf16 g_q2  [(long)BB*LL*2*DHH];      // Q        [hi|lo]
__device__ bf16 g_k2  [(long)BB*WW*2*DHH];      // K seq    [hi|lo]
__device__ bf16 g_v2  [(long)BB*2*WW*DHH];      // V seq    [hi;lo] stacked
__device__ bf16 g_kc2 [(long)BB*KC*2*DHH];      // K cache
__device__ bf16 g_vc2 [(long)BB*2*KC*DHH];      // V cache stacked
__device__ bf16 g_p2  [(long)BB*LL*2*WW];       // P seq / FFN mid [hi|lo]
__device__ bf16 g_pc2 [(long)BB*LL*2*KC];       // P cache [hi|lo]
__device__ bf16 g_cat2[(long)BB*LL*2*DD];       // concat attn out [hi|lo]
#define WL 6291456L                              // split weights per layer (elements)
__device__ bf16 g_w2  [4*WL];
// per-layer offsets inside g_w2
#define OQ  0L
#define OK_ 262144L
#define OV  524288L
#define OQC 786432L
#define OKCo 1048576L
#define OVC 1310720L
#define OWO 1572864L
#define OF1 2097152L
#define OF2 4194304L

#define FLAG_RES  1
#define FLAG_RELU 2

// ---------------------------------------------------------------------------
// Elementwise kernels
// ---------------------------------------------------------------------------
__global__ void embed_kernel(const int* __restrict__ cache, const int* __restrict__ seq,
                             const float* __restrict__ item, const float* __restrict__ cpos,
                             const float* __restrict__ spos, const float* __restrict__ seg,
                             float* __restrict__ h) {
    int r = blockIdx.x;
    int b = r / LL, l = r % LL;
    int idx; const float* pos; const float* sg;
    if (l < KC) { idx = cache[b * KC + l]; pos = cpos + (long)l * DD; sg = seg; }
    else        { int i = l - KC; idx = seq[b * WW + i]; pos = spos + (long)i * DD; sg = seg + DD; }
    const float* it = item + (long)idx * DD;
    float* hr = h + (long)r * DD;
    for (int d = threadIdx.x; d < DD; d += blockDim.x)
        hr[d] = it[d] + pos[d] + sg[d];
}

// split fp32 -> (hi, lo) bf16
__global__ void split_kernel(const float* __restrict__ src, bf16* __restrict__ hi,
                             bf16* __restrict__ lo, long n) {
    long i = blockIdx.x * 256L + threadIdx.x;
    if (i < n) {
        float v = src[i];
        bf16 hh = __float2bfloat16_rn(v);
        hi[i] = hh;
        lo[i] = __float2bfloat16_rn(v - __bfloat162float(hh));
    }
}

// LayerNorm, split output row [hi(0..D-1) | lo(D..2D-1)], stride 2D
__global__ void ln_split_kernel(const float* __restrict__ x, bf16* __restrict__ y,
                                const float* __restrict__ g, const float* __restrict__ bia) {
    __shared__ float rs[256], rq[256];
    long row = (long)blockIdx.y * LL + blockIdx.x;
    const float* xr = x + row * DD;
    bf16* yr = y + row * (2 * DD);
    int t = threadIdx.x;
    float v0 = xr[t], v1 = xr[t + 256];
    rs[t] = v0 + v1; rq[t] = v0 * v0 + v1 * v1; __syncthreads();
    for (int o = 128; o > 0; o >>= 1) {
        if (t < o) { rs[t] += rs[t + o]; rq[t] += rq[t + o]; }
        __syncthreads();
    }
    float mean = rs[0] * (1.0f / DD);
    float inv  = rsqrtf(rq[0] * (1.0f / DD) - mean * mean + LN_EPS);
    float o0 = (v0 - mean) * inv * g[t]       + bia[t];
    float o1 = (v1 - mean) * inv * g[t + 256] + bia[t + 256];
    bf16 h0 = __float2bfloat16_rn(o0), h1 = __float2bfloat16_rn(o1);
    yr[t]            = h0;
    yr[t + 256]      = h1;
    yr[DD + t]       = __float2bfloat16_rn(o0 - __bfloat162float(h0));
    yr[DD + t + 256] = __float2bfloat16_rn(o1 - __bfloat162float(h1));
}

// softmax fp32 scores -> split bf16 P (row [hi|lo], stride 2*ncols); masked tail zeroed
__global__ void softmax_split_kernel(float* __restrict__ S, bf16* __restrict__ P,
                                     int ncols, int causal) {
    __shared__ float red[256];
    int l = blockIdx.x, b = blockIdx.y;
    float* p = S + ((long)b * LL + l) * ncols;
    bf16*  d = P + ((long)b * LL + l) * (2 * ncols);
    int valid = causal ? (l < KC ? ncols : (l - KC + 1)) : ncols;
    int t = threadIdx.x;

    float m = -1e30f;
    for (int i = t; i < valid; i += blockDim.x) m = fmaxf(m, p[i]);
    red[t] = m; __syncthreads();
    for (int o = 128; o > 0; o >>= 1) { if (t < o) red[t] = fmaxf(red[t], red[t + o]); __syncthreads(); }
    m = red[0]; __syncthreads();

    float s = 0.f;
    for (int i = t; i < valid; i += blockDim.x) { float e = expf(p[i] - m); p[i] = e; s += e; }
    red[t] = s; __syncthreads();
    for (int o = 128; o > 0; o >>= 1) { if (t < o) red[t] += red[t + o]; __syncthreads(); }
    float inv = 1.0f / red[0];

    for (int i = t; i < ncols; i += blockDim.x) {
        float v = (i < valid) ? p[i] * inv : 0.f;
        bf16 hh = __float2bfloat16_rn(v);
        d[i]         = hh;
        d[ncols + i] = __float2bfloat16_rn(v - __bfloat162float(hh));
    }
}

__global__ void final_kernel(const float* __restrict__ h, const float* __restrict__ fg,
                             const float* __restrict__ fb, const float* __restrict__ wev,
                             const float* __restrict__ bev, float* __restrict__ out) {
    __shared__ float rs[256], rq[256];
    int l = blockIdx.x, b = blockIdx.y;
    const float* xr = h + ((long)b * LL + l) * DD;
    int t = threadIdx.x;
    float v0 = xr[t], v1 = xr[t + 256];
    rs[t] = v0 + v1; rq[t] = v0 * v0 + v1 * v1; __syncthreads();
    for (int o = 128; o > 0; o >>= 1) {
        if (t < o) { rs[t] += rs[t + o]; rq[t] += rq[t + o]; }
        __syncthreads();
    }
    float mean = rs[0] * (1.0f / DD);
    float inv  = rsqrtf(rq[0] * (1.0f / DD) - mean * mean + LN_EPS);
    __syncthreads();
    float d0 = ((v0 - mean) * inv * fg[t]       + fb[t])       * wev[t];
    float d1 = ((v1 - mean) * inv * fg[t + 256] + fb[t + 256]) * wev[t + 256];
    rs[t] = d0 + d1; __syncthreads();
    for (int o = 128; o > 0; o >>= 1) { if (t < o) rs[t] += rs[t + o]; __syncthreads(); }
    if (t == 0) out[b * KC + l] = rs[0] + bev[0];
}

// ---------------------------------------------------------------------------
// bf16x3 GEMM via 3 virtual K-segments over pre-split operands.
// A: (M x 2*KH) [hi|lo] row-major. B:
//   BSTYLE 0: (2*KH x N)  k-major [hi;lo] stacked rows
//   BSTYLE 1: (N x 2*KH)  [hi|lo] row-major (B^T)
// Block 128x128, 8 warps (2x4), warp 64x32, mma m16n8k16 bf16, fp32 accum.
// cp.async 3-stage pipeline; ldmatrix fragment loads; padded strides for
// bank-conflict-free LDSM (A rows 80B, B-notrans rows 272B).
// ---------------------------------------------------------------------------
__device__ __forceinline__ void mma_bf16(float* c, const unsigned* a, const unsigned* b) {
    asm volatile(
        "mma.sync.aligned.m16n8k16.row.col.f32.bf16.bf16.f32 "
        "{%0,%1,%2,%3}, {%4,%5,%6,%7}, {%8,%9}, {%0,%1,%2,%3};"
        : "+f"(c[0]), "+f"(c[1]), "+f"(c[2]), "+f"(c[3])
        : "r"(a[0]), "r"(a[1]), "r"(a[2]), "r"(a[3]), "r"(b[0]), "r"(b[1]));
}

__device__ __forceinline__ void cpasync16(unsigned daddr, const void* src) {
    asm volatile("cp.async.cg.shared.global [%0], [%1], 16;" :: "r"(daddr), "l"(src));
}

#define ST_BYTES 10240

template <int BSTYLE>
__global__ __launch_bounds__(256)
void gemm3(const bf16* __restrict__ A, int lda, long sA,
           const bf16* __restrict__ B, int ldb, long sB,
           int M, int N, int KH,
           float* Cf, int ldcf, long sCf,
           bf16* Chi, bf16* Clo, int ldc2, long sC2,
           const float* __restrict__ bias, float alpha, int flags) {
    extern __shared__ __align__(16) unsigned char smraw[];
    unsigned aS = (unsigned)__cvta_generic_to_shared(smraw);
    unsigned bS = aS + 3 * ST_BYTES;

    A += (long)blockIdx.z * sA;
    B += (long)blockIdx.z * sB;
    if (Cf)  Cf  += (long)blockIdx.z * sCf;
    if (Chi) { Chi += (long)blockIdx.z * sC2; Clo += (long)blockIdx.z * sC2; }

    const int m0 = blockIdx.y * 128, n0 = blockIdx.x * 128;
    const int tid  = threadIdx.x;
    const int lane = tid & 31;
    const int warp = tid >> 5;
    const int wm = (warp >> 2) * 64;
    const int wn = (warp & 3) * 32;
    const int r = lane >> 2, c = lane & 3;

    float acc[4][4][4] = {{{0.f}}};

    const int segs = KH >> 5;
    const int KT = segs * 3;

    auto stage = [&](int st, int kt) {
        int sgi = (kt >= segs) + (kt >= 2 * segs);
        int ko = (kt - sgi * segs) << 5;
        int ao = ko + (sgi == 1 ? KH : 0);
        int bo = ko + (sgi == 2 ? KH : 0);
        unsigned ab = aS + st * ST_BYTES;
        unsigned bb = bS + st * ST_BYTES;
        int ch = tid * 2;
#pragma unroll
        for (int i = 0; i < 2; i++) {
            int cc2 = ch + i;
            int row = cc2 >> 2, c16 = cc2 & 3;
            const bf16* src = A + (long)min(m0 + row, M - 1) * lda + ao + c16 * 8;
            cpasync16(ab + row * 80 + c16 * 16, src);
        }
        if (BSTYLE == 1) {
#pragma unroll
            for (int i = 0; i < 2; i++) {
                int cc2 = ch + i;
                int row = cc2 >> 2, c16 = cc2 & 3;
                const bf16* src = B + (long)min(n0 + row, N - 1) * ldb + bo + c16 * 8;
                cpasync16(bb + row * 80 + c16 * 16, src);
            }
        } else {
#pragma unroll
            for (int i = 0; i < 2; i++) {
                int cc2 = ch + i;
                int row = cc2 >> 4, c16 = cc2 & 15;
                int col = min(n0 + c16 * 8, N - 8);
                const bf16* src = B + (long)(bo + row) * ldb + col;
                cpasync16(bb + row * 272 + c16 * 16, src);
            }
        }
    };

    stage(0, 0);
    asm volatile("cp.async.commit_group;");
    if (KT > 1) stage(1, 1);
    asm volatile("cp.async.commit_group;");

    for (int kt = 0; kt < KT; kt++) {
        if (kt + 2 < KT) stage((kt + 2) % 3, kt + 2);
        asm volatile("cp.async.commit_group;");
        asm volatile("cp.async.wait_group 2;");
        __syncthreads();

        const int st = kt % 3;
        const unsigned ab = aS + st * ST_BYTES;
        const unsigned bb = bS + st * ST_BYTES;
#pragma unroll
        for (int kh = 0; kh < 2; kh++) {
            unsigned a[4][4];
#pragma unroll
            for (int mf = 0; mf < 4; mf++) {
                int row = wm + mf * 16 + (lane & 15);
                unsigned ad = ab + row * 80 + (kh * 2 + (lane >> 4)) * 16;
                asm volatile("ldmatrix.sync.aligned.m8n8.x4.shared.b16 {%0,%1,%2,%3}, [%4];"
                             : "=r"(a[mf][0]), "=r"(a[mf][1]), "=r"(a[mf][2]), "=r"(a[mf][3])
                             : "r"(ad));
            }
            unsigned bfr[4][2];
#pragma unroll
            for (int nfp = 0; nfp < 2; nfp++) {
                int g = lane >> 3, rr2 = lane & 7;
                if (BSTYLE == 1) {
                    int row = wn + nfp * 16 + ((g >> 1) & 1) * 8 + rr2;
                    unsigned ad = bb + row * 80 + (kh * 2 + (g & 1)) * 16;
                    asm volatile("ldmatrix.sync.aligned.m8n8.x4.shared.b16 {%0,%1,%2,%3}, [%4];"
                                 : "=r"(bfr[nfp*2][0]), "=r"(bfr[nfp*2][1]),
                                   "=r"(bfr[nfp*2+1][0]), "=r"(bfr[nfp*2+1][1])
                                 : "r"(ad));
                } else {
                    int row = kh * 16 + (g & 1) * 8 + rr2;
                    int c16 = ((wn + nfp * 16) >> 3) + ((g >> 1) & 1);
                    unsigned ad = bb + row * 272 + c16 * 16;
                    asm volatile("ldmatrix.sync.aligned.m8n8.x4.trans.shared.b16 {%0,%1,%2,%3}, [%4];"
                                 : "=r"(bfr[nfp*2][0]), "=r"(bfr[nfp*2][1]),
                                   "=r"(bfr[nfp*2+1][0]), "=r"(bfr[nfp*2+1][1])
                                 : "r"(ad));
                }
            }
#pragma unroll
            for (int mf = 0; mf < 4; mf++)
#pragma unroll
                for (int nf = 0; nf < 4; nf++)
                    mma_bf16(acc[mf][nf], a[mf], bfr[nf]);
        }
        __syncthreads();
    }

    // ---- epilogue ----
#pragma unroll
    for (int mf = 0; mf < 4; mf++) {
        int r0 = m0 + wm + mf * 16 + r;
#pragma unroll
        for (int nf = 0; nf < 4; nf++) {
            int cc = n0 + wn + nf * 8 + c * 2;
            if (cc < N) {
#pragma unroll
                for (int half = 0; half < 2; half++) {
                    int rr = r0 + half * 8;
                    if (rr < M) {
                        float v0 = alpha * acc[mf][nf][half * 2 + 0];
                        float v1 = alpha * acc[mf][nf][half * 2 + 1];
                        if (bias) { v0 += bias[cc]; v1 += bias[cc + 1]; }
                        if (flags & FLAG_RELU) { v0 = fmaxf(v0, 0.f); v1 = fmaxf(v1, 0.f); }
                        if (Cf) {
                            long base = (long)rr * ldcf + cc;
                            float w0 = v0, w1 = v1;
                            if (flags & FLAG_RES) { w0 += Cf[base]; w1 += Cf[base + 1]; }
                            Cf[base] = w0; Cf[base + 1] = w1;
                        }
                        if (Chi) {
                            long base = (long)rr * ldc2 + cc;
                            bf16 h0 = __float2bfloat16_rn(v0);
                            bf16 h1 = __float2bfloat16_rn(v1);
                            Chi[base]     = h0;
                            Chi[base + 1] = h1;
                            Clo[base]     = __float2bfloat16_rn(v0 - __bfloat162float(h0));
                            Clo[base + 1] = __float2bfloat16_rn(v1 - __bfloat162float(h1));
                        }
                    }
                }
            }
        }
    }
}

// ---------------------------------------------------------------------------
// Host launcher
// ---------------------------------------------------------------------------
static void G3(int bstyle, const bf16* A, int lda, long sA,
               const bf16* B, int ldb, long sB,
               int M, int N, int KH,
               float* Cf, int ldcf, long sCf,
               bf16* Chi, bf16* Clo, int ldc2, long sC2,
               const float* bias, float alpha, int flags) {
    dim3 grid((N + 127) / 128, (M + 127) / 128, BB);
    size_t sh = 6 * ST_BYTES;
    if (bstyle)
        gemm3<1><<<grid, 256, sh>>>(A, lda, sA, B, ldb, sB, M, N, KH,
                                    Cf, ldcf, sCf, Chi, Clo, ldc2, sC2, bias, alpha, flags);
    else
        gemm3<0><<<grid, 256, sh>>>(A, lda, sA, B, ldb, sB, M, N, KH,
                                    Cf, ldcf, sCf, Chi, Clo, ldc2, sC2, bias, alpha, flags);
}

extern "C" void kernel_launch(void* const* d_in, const int* in_sizes, int n_in,
                              void* d_out, int out_size) {
    const int*   cache = (const int*)d_in[0];
    const int*   seq   = (const int*)d_in[1];
    const float* item  = (const float*)d_in[2];
    const float* cpos  = (const float*)d_in[3];
    const float* spos  = (const float*)d_in[4];
    const float* seg   = (const float*)d_in[5];
    const float* wq_s  = (const float*)d_in[6];
    const float* wk_s  = (const float*)d_in[7];
    const float* wv_s  = (const float*)d_in[8];
    const float* wq_c  = (const float*)d_in[9];
    const float* wk_c  = (const float*)d_in[10];
    const float* wv_c  = (const float*)d_in[11];
    const float* w_out = (const float*)d_in[12];
    const float* b_out = (const float*)d_in[13];
    const float* ln1g  = (const float*)d_in[14];
    const float* ln1b  = (const float*)d_in[15];
    const float* ln2g  = (const float*)d_in[16];
    const float* ln2b  = (const float*)d_in[17];
    const float* wff1  = (const float*)d_in[18];
    const float* bff1  = (const float*)d_in[19];
    const float* wff2  = (const float*)d_in[20];
    const float* bff2  = (const float*)d_in[21];
    const float* fing  = (const float*)d_in[22];
    const float* finb  = (const float*)d_in[23];
    const float* wev   = (const float*)d_in[24];
    const float* bev   = (const float*)d_in[25];
    float* out = (float*)d_out;

    cudaFuncSetAttribute(gemm3<0>, cudaFuncAttributeMaxDynamicSharedMemorySize, 6 * ST_BYTES);
    cudaFuncSetAttribute(gemm3<1>, cudaFuncAttributeMaxDynamicSharedMemorySize, 6 * ST_BYTES);

    float *h, *s;
    bf16 *hn2, *q2, *k2, *v2, *kc2, *vc2, *p2, *pc2, *cat2, *w2;
    cudaGetSymbolAddress((void**)&h,   g_h);
    cudaGetSymbolAddress((void**)&s,   g_s);
    cudaGetSymbolAddress((void**)&hn2, g_hn2);
    cudaGetSymbolAddress((void**)&q2,  g_q2);
    cudaGetSymbolAddress((void**)&k2,  g_k2);
    cudaGetSymbolAddress((void**)&v2,  g_v2);
    cudaGetSymbolAddress((void**)&kc2, g_kc2);
    cudaGetSymbolAddress((void**)&vc2, g_vc2);
    cudaGetSymbolAddress((void**)&p2,  g_p2);
    cudaGetSymbolAddress((void**)&pc2, g_pc2);
    cudaGetSymbolAddress((void**)&cat2,g_cat2);
    cudaGetSymbolAddress((void**)&w2,  g_w2);

    const float scale = 0.0625f;   // 1/sqrt(256)

    // ---- split all weights (stacked [hi;lo]) ----
    for (int l = 0; l < NLL; l++) {
        bf16* wb = w2 + l * WL;
        auto SPL = [&](const float* src, bf16* dst, long els) {
            split_kernel<<<(unsigned)((els + 255) / 256), 256>>>(src, dst, dst + els, els);
        };
        SPL(wq_s + (long)l * DD * DHH,  wb + OQ,   (long)DD * DHH);
        SPL(wk_s + (long)l * DD * DHH,  wb + OK_,  (long)DD * DHH);
        SPL(wv_s + (long)l * DD * DHH,  wb + OV,   (long)DD * DHH);
        SPL(wq_c + (long)l * DD * DHH,  wb + OQC,  (long)DD * DHH);
        SPL(wk_c + (long)l * DD * DHH,  wb + OKCo, (long)DD * DHH);
        SPL(wv_c + (long)l * DD * DHH,  wb + OVC,  (long)DD * DHH);
        SPL(w_out + (long)l * DD * DD,  wb + OWO,  (long)DD * DD);
        SPL(wff1 + (long)l * DD * DFFF, wb + OF1,  (long)DD * DFFF);
        SPL(wff2 + (long)l * DFFF * DD, wb + OF2,  (long)DFFF * DD);
    }

    embed_kernel<<<BB * LL, 256>>>(cache, seq, item, cpos, spos, seg, h);

    for (int l = 0; l < NLL; l++) {
        bf16* wb = w2 + l * WL;
        const float* Bo = b_out + (long)l * DD;
        const float* B1 = bff1 + (long)l * DFFF;
        const float* B2 = bff2 + (long)l * DD;

        const int Mq = (l == NLL - 1) ? KC : LL;

        // ---- LN1 (all rows: K/V need them) ----
        ln_split_kernel<<<dim3(LL, BB), 256>>>(h, hn2, ln1g + l * DD, ln1b + l * DD);

        // ---- Attention A (seq keys, causal) ----
        G3(0, hn2, 2*DD, (long)LL*2*DD, wb + OQ, DHH, 0, Mq, DHH, DD,
           0, 0, 0, q2, q2 + DHH, 2*DHH, (long)LL*2*DHH, 0, 1.f, 0);
        G3(0, hn2 + (long)KC*2*DD, 2*DD, (long)LL*2*DD, wb + OK_, DHH, 0, WW, DHH, DD,
           0, 0, 0, k2, k2 + DHH, 2*DHH, (long)WW*2*DHH, 0, 1.f, 0);
        G3(0, hn2 + (long)KC*2*DD, 2*DD, (long)LL*2*DD, wb + OV, DHH, 0, WW, DHH, DD,
           0, 0, 0, v2, v2 + (long)WW*DHH, DHH, (long)2*WW*DHH, 0, 1.f, 0);
        G3(1, q2, 2*DHH, (long)LL*2*DHH, k2, 2*DHH, (long)WW*2*DHH, Mq, WW, DHH,
           s, WW, (long)LL*WW, 0, 0, 0, 0, 0, scale, 0);
        softmax_split_kernel<<<dim3(Mq, BB), 256>>>(s, p2, WW, 1);
        G3(0, p2, 2*WW, (long)LL*2*WW, v2, DHH, (long)2*WW*DHH, Mq, DHH, WW,
           0, 0, 0, cat2, cat2 + DD, 2*DD, (long)LL*2*DD, 0, 1.f, 0);

        // ---- Attention B (cache keys) ----
        G3(0, hn2, 2*DD, (long)LL*2*DD, wb + OQC, DHH, 0, Mq, DHH, DD,
           0, 0, 0, q2, q2 + DHH, 2*DHH, (long)LL*2*DHH, 0, 1.f, 0);
        G3(0, hn2, 2*DD, (long)LL*2*DD, wb + OKCo, DHH, 0, KC, DHH, DD,
           0, 0, 0, kc2, kc2 + DHH, 2*DHH, (long)KC*2*DHH, 0, 1.f, 0);
        G3(0, hn2, 2*DD, (long)LL*2*DD, wb + OVC, DHH, 0, KC, DHH, DD,
           0, 0, 0, vc2, vc2 + (long)KC*DHH, DHH, (long)2*KC*DHH, 0, 1.f, 0);
        G3(1, q2, 2*DHH, (long)LL*2*DHH, kc2, 2*DHH, (long)KC*2*DHH, Mq, KC, DHH,
           s, KC, (long)LL*KC, 0, 0, 0, 0, 0, scale, 0);
        softmax_split_kernel<<<dim3(Mq, BB), 256>>>(s, pc2, KC, 0);
        G3(0, pc2, 2*KC, (long)LL*2*KC, vc2, DHH, (long)2*KC*DHH, Mq, DHH, KC,
           0, 0, 0, cat2 + DHH, cat2 + DD + DHH, 2*DD, (long)LL*2*DD, 0, 1.f, 0);

        // ---- Output projection + residual ----
        G3(0, cat2, 2*DD, (long)LL*2*DD, wb + OWO, DD, 0, Mq, DD, DD,
           h, DD, (long)LL*DD, 0, 0, 0, 0, Bo, 1.f, FLAG_RES);

        // ---- FFN ----
        ln_split_kernel<<<dim3(Mq, BB), 256>>>(h, hn2, ln2g + l * DD, ln2b + l * DD);
        G3(0, hn2, 2*DD, (long)LL*2*DD, wb + OF1, DFFF, 0, Mq, DFFF, DD,
           0, 0, 0, p2, p2 + DFFF, 2*DFFF, (long)LL*2*DFFF, B1, 1.f, FLAG_RELU);
        G3(0, p2, 2*DFFF, (long)LL*2*DFFF, wb + OF2, DD, 0, Mq, DD, DFFF,
           h, DD, (long)LL*DD, 0, 0, 0, 0, B2, 1.f, FLAG_RES);
    }

    final_kernel<<<dim3(KC, BB), 256>>>(h, fing, finb, wev, bev, out);
}